// round 2
// baseline (speedup 1.0000x reference)
#include <cuda_runtime.h>

#define NMAX 100352
#define D 128
#define ALPHA 0.5f

// ---- scratch (static device globals; no allocation) ----
__device__ float4 g_agg_in[NMAX * 32];   // N x 128 fp32 accumulators (in-neighbor sums)
__device__ float4 g_agg_out[NMAX * 32];  // N x 128 fp32 accumulators (out-neighbor sums)
__device__ int    g_cnt_in[NMAX];
__device__ int    g_cnt_out[NMAX];
__device__ int    g_idx64;               // 1 if edge_index is int64, 0 if int32

__device__ __forceinline__ void red_add_f4(float4* p, float4 v) {
    asm volatile("red.global.add.v4.f32 [%0], {%1,%2,%3,%4};"
                 :: "l"(p), "f"(v.x), "f"(v.y), "f"(v.z), "f"(v.w) : "memory");
}

// ---- probe edge_index dtype (deterministic, data-driven) ----
__global__ void detect_kernel(const long long* ei64, int E, int n) {
    if (blockIdx.x == 0 && threadIdx.x == 0) {
        int is64 = 1;
        int m = E < 64 ? E : 64;   // stay within first E int64 slots (valid either way)
        for (int i = 0; i < m; i++) {
            long long v = ei64[i];
            if (v < 0 || v >= (long long)n) { is64 = 0; break; }
        }
        g_idx64 = is64;
    }
}

// ---- zero scratch each call (deterministic work every launch) ----
__global__ void zero_kernel(int n) {
    const int total4 = n * 32;
    const float4 z = make_float4(0.f, 0.f, 0.f, 0.f);
    for (int i = blockIdx.x * blockDim.x + threadIdx.x; i < total4;
         i += gridDim.x * blockDim.x) {
        g_agg_in[i]  = z;
        g_agg_out[i] = z;
    }
    for (int i = blockIdx.x * blockDim.x + threadIdx.x; i < n;
         i += gridDim.x * blockDim.x) {
        g_cnt_in[i]  = 0;
        g_cnt_out[i] = 0;
    }
}

// ---- one warp per edge: scatter x[src]->agg_in[dst], x[dst]->agg_out[src] ----
__global__ void edge_kernel(const float4* __restrict__ x4,
                            const void* __restrict__ ei_raw,
                            int E) {
    int gid  = blockIdx.x * blockDim.x + threadIdx.x;
    int e    = gid >> 5;
    int lane = gid & 31;
    if (e >= E) return;
    int s, d;
    if (g_idx64) {
        const long long* ei = (const long long*)ei_raw;
        s = (int)ei[e];
        d = (int)ei[E + e];
    } else {
        const int* ei = (const int*)ei_raw;
        s = ei[e];
        d = ei[E + e];
    }
    float4 xs = x4[s * 32 + lane];
    float4 xd = x4[d * 32 + lane];
    red_add_f4(&g_agg_in[d * 32 + lane], xs);
    red_add_f4(&g_agg_out[s * 32 + lane], xd);
    if (lane == 0) {
        atomicAdd(&g_cnt_in[d], 1);
        atomicAdd(&g_cnt_out[s], 1);
    }
}

// ---- fused GEMM: out = [x | agg_in/cnt | agg_out/cnt] @ [Wself; (1-a)Ws2d; a*Wd2s] + bias
// BM=128, BN=128, BK=32, 256 threads, 8x8 per thread.
__global__ __launch_bounds__(256, 2)
void gemm_kernel(const float* __restrict__ x,
                 const float* __restrict__ Wself, const float* __restrict__ bself,
                 const float* __restrict__ Ws2d,  const float* __restrict__ bs2d,
                 const float* __restrict__ Wd2s,  const float* __restrict__ bd2s,
                 float* __restrict__ out, int n) {
    __shared__ float As[32][132];   // transposed A tile, padded (conflict-free)
    __shared__ float Bs[32][128];
    __shared__ float rcpin[128], rcpout[128];

    const int tid  = threadIdx.x;
    const int row0 = blockIdx.x * 128;

    if (tid < 128) {
        int r = row0 + tid;
        float ci = 1.f, co = 1.f;
        if (r < n) {
            ci = (float)max(g_cnt_in[r], 1);
            co = (float)max(g_cnt_out[r], 1);
        }
        rcpin[tid]  = 1.f / ci;
        rcpout[tid] = 1.f / co;
    }
    __syncthreads();

    const int tx = tid & 15, ty = tid >> 4;
    float acc[8][8];
#pragma unroll
    for (int i = 0; i < 8; i++)
#pragma unroll
        for (int j = 0; j < 8; j++) acc[i][j] = 0.f;

    const float* aggin  = (const float*)g_agg_in;
    const float* aggout = (const float*)g_agg_out;

    for (int kk = 0; kk < 12; kk++) {
        const int kofs = kk * 32;
        const int seg  = kofs >> 7;    // 0: x, 1: agg_in, 2: agg_out
        const int kseg = kofs & 127;   // k offset within the 128-wide segment

        // ---- load A tile (128 rows x 32 k), constructed on the fly ----
#pragma unroll
        for (int i = 0; i < 4; i++) {
            int idx = tid + i * 256;       // 0..1023
            int row = idx >> 3;            // 0..127
            int k4  = idx & 7;             // float4 index within 32-k chunk
            int r   = row0 + row;
            float4 v = make_float4(0.f, 0.f, 0.f, 0.f);
            if (r < n) {
                int col = kseg + k4 * 4;
                if (seg == 0) {
                    v = *(const float4*)&x[r * 128 + col];
                } else if (seg == 1) {
                    v = *(const float4*)&aggin[r * 128 + col];
                    float sc = rcpin[row];
                    v.x *= sc; v.y *= sc; v.z *= sc; v.w *= sc;
                } else {
                    v = *(const float4*)&aggout[r * 128 + col];
                    float sc = rcpout[row];
                    v.x *= sc; v.y *= sc; v.z *= sc; v.w *= sc;
                }
            }
            int kb = k4 * 4;
            As[kb + 0][row] = v.x;
            As[kb + 1][row] = v.y;
            As[kb + 2][row] = v.z;
            As[kb + 3][row] = v.w;
        }

        // ---- load B tile (32 k x 128 cols), scaled per segment ----
        const float* W  = (seg == 0) ? Wself : ((seg == 1) ? Ws2d : Wd2s);
        const float coef = (seg == 0) ? 1.0f : ((seg == 1) ? (1.0f - ALPHA) : ALPHA);
#pragma unroll
        for (int i = 0; i < 4; i++) {
            int idx = tid + i * 256;
            int kl  = idx >> 5;            // 0..31
            int j4  = idx & 31;            // 0..31 (float4 col)
            float4 w = *(const float4*)&W[(kseg + kl) * 128 + j4 * 4];
            w.x *= coef; w.y *= coef; w.z *= coef; w.w *= coef;
            *(float4*)&Bs[kl][j4 * 4] = w;
        }
        __syncthreads();

        // ---- compute 8x8 per thread ----
#pragma unroll
        for (int k = 0; k < 32; k++) {
            float a[8], b[8];
            *(float4*)(a)     = *(const float4*)&As[k][ty * 8];
            *(float4*)(a + 4) = *(const float4*)&As[k][ty * 8 + 4];
            *(float4*)(b)     = *(const float4*)&Bs[k][tx * 8];
            *(float4*)(b + 4) = *(const float4*)&Bs[k][tx * 8 + 4];
#pragma unroll
            for (int ii = 0; ii < 8; ii++)
#pragma unroll
                for (int jj = 0; jj < 8; jj++)
                    acc[ii][jj] += a[ii] * b[jj];
        }
        __syncthreads();
    }

    // ---- epilogue: bias + store ----
    float bias[8];
#pragma unroll
    for (int jj = 0; jj < 8; jj++) {
        int j = tx * 8 + jj;
        bias[jj] = bself[j] + (1.0f - ALPHA) * bs2d[j] + ALPHA * bd2s[j];
    }
#pragma unroll
    for (int ii = 0; ii < 8; ii++) {
        int r = row0 + ty * 8 + ii;
        if (r < n) {
            float4 v0, v1;
            v0.x = acc[ii][0] + bias[0]; v0.y = acc[ii][1] + bias[1];
            v0.z = acc[ii][2] + bias[2]; v0.w = acc[ii][3] + bias[3];
            v1.x = acc[ii][4] + bias[4]; v1.y = acc[ii][5] + bias[5];
            v1.z = acc[ii][6] + bias[6]; v1.w = acc[ii][7] + bias[7];
            *(float4*)&out[r * 128 + tx * 8]     = v0;
            *(float4*)&out[r * 128 + tx * 8 + 4] = v1;
        }
    }
}

extern "C" void kernel_launch(void* const* d_in, const int* in_sizes, int n_in,
                              void* d_out, int out_size) {
    const float* x     = (const float*)d_in[0];
    const float* Wself = (const float*)d_in[1];
    const float* bself = (const float*)d_in[2];
    const float* Ws2d  = (const float*)d_in[3];
    const float* bs2d  = (const float*)d_in[4];
    const float* Wd2s  = (const float*)d_in[5];
    const float* bd2s  = (const float*)d_in[6];
    const void*  ei    = d_in[7];

    const int n = in_sizes[0] / 128;
    const int E = in_sizes[7] / 2;

    float* out = (float*)d_out;

    detect_kernel<<<1, 32>>>((const long long*)ei, E, n);
    zero_kernel<<<2048, 256>>>(n);

    int eblocks = (E * 32 + 255) / 256;   // one warp per edge
    edge_kernel<<<eblocks, 256>>>((const float4*)x, ei, E);

    int gblocks = (n + 127) / 128;
    gemm_kernel<<<gblocks, 256>>>(x, Wself, bself, Ws2d, bs2d, Wd2s, bd2s, out, n);
}

// round 4
// speedup vs baseline: 1.0266x; 1.0266x over previous
#include <cuda_runtime.h>
#include <cstdint>

#define NMAX 100352
#define ALPHA 0.5f

// ---- scratch (static device globals; no allocation) ----
__device__ float4 g_agg_in[NMAX * 32];   // N x 128 fp32 in-neighbor sums
__device__ float4 g_agg_out[NMAX * 32];  // N x 128 fp32 out-neighbor sums
__device__ int    g_cnt_in[NMAX];
__device__ int    g_cnt_out[NMAX];
__device__ int    g_idx64;               // 1 if edge_index is int64, 0 if int32
__device__ float  g_Wpre[12 * 32 * 128]; // coef-scaled W, chunk-major [kc][k][n]

// =============================== helpers ===================================
__device__ __forceinline__ void red_add_f4(float4* p, float4 v) {
    asm volatile("red.global.add.v4.f32 [%0], {%1,%2,%3,%4};"
                 :: "l"(p), "f"(v.x), "f"(v.y), "f"(v.z), "f"(v.w) : "memory");
}
__device__ __forceinline__ uint32_t smem_u32(const void* p) {
    uint32_t a;
    asm("{ .reg .u64 t; cvta.to.shared.u64 t, %1; cvt.u32.u64 %0, t; }" : "=r"(a) : "l"(p));
    return a;
}
__device__ __forceinline__ void cp_async16(uint32_t saddr, const void* g) {
    asm volatile("cp.async.cg.shared.global [%0], [%1], 16;"
                 :: "r"(saddr), "l"(g) : "memory");
}
__device__ __forceinline__ void cp_commit() {
    asm volatile("cp.async.commit_group;" ::: "memory");
}
__device__ __forceinline__ void cp_wait0() {
    asm volatile("cp.async.wait_group 0;" ::: "memory");
}

// ============================ small kernels ================================
__global__ void detect_kernel(const long long* ei64, int E, int n) {
    int lane = threadIdx.x;                 // 32 threads
    int m = E < 64 ? E : 64;
    bool bad = false;
    for (int i = lane; i < m; i += 32) {
        long long v = ei64[i];
        if (v < 0 || v >= (long long)n) bad = true;
    }
    unsigned any = __ballot_sync(0xFFFFFFFFu, bad);
    if (lane == 0) g_idx64 = (any == 0) ? 1 : 0;
}

__global__ void zero_kernel(int n) {
    const int total4 = n * 32;
    const float4 z = make_float4(0.f, 0.f, 0.f, 0.f);
    for (int i = blockIdx.x * blockDim.x + threadIdx.x; i < total4;
         i += gridDim.x * blockDim.x) {
        g_agg_in[i]  = z;
        g_agg_out[i] = z;
    }
    for (int i = blockIdx.x * blockDim.x + threadIdx.x; i < n;
         i += gridDim.x * blockDim.x) {
        g_cnt_in[i]  = 0;
        g_cnt_out[i] = 0;
    }
}

// Fold coef into W, reorder chunk-major: g_Wpre[kc*4096 + k*128 + n]
__global__ void prep_w_kernel(const float* __restrict__ Wself,
                              const float* __restrict__ Ws2d,
                              const float* __restrict__ Wd2s) {
    int tid = blockIdx.x * blockDim.x + threadIdx.x;
    if (tid >= 12 * 4096) return;
    int kc  = tid >> 12;
    int rem = tid & 4095;
    int kl  = rem >> 7;        // 0..31
    int nc  = rem & 127;
    int kglob  = kc * 32 + kl;
    int seg    = kglob >> 7;
    int klocal = kglob & 127;
    const float* W = seg == 0 ? Wself : (seg == 1 ? Ws2d : Wd2s);
    float coef = seg == 0 ? 1.0f : 0.5f;
    g_Wpre[tid] = W[klocal * 128 + nc] * coef;
}

// ---- one warp per edge: scatter x[src]->agg_in[dst], x[dst]->agg_out[src] ----
__global__ void edge_kernel(const float4* __restrict__ x4,
                            const void* __restrict__ ei_raw,
                            int E) {
    int gid  = blockIdx.x * blockDim.x + threadIdx.x;
    int e    = gid >> 5;
    int lane = gid & 31;
    if (e >= E) return;
    int s, d;
    if (g_idx64) {
        const long long* ei = (const long long*)ei_raw;
        s = (int)ei[e];
        d = (int)ei[E + e];
    } else {
        const int* ei = (const int*)ei_raw;
        s = ei[e];
        d = ei[E + e];
    }
    float4 xs = x4[s * 32 + lane];
    float4 xd = x4[d * 32 + lane];
    red_add_f4(&g_agg_in[d * 32 + lane], xs);
    red_add_f4(&g_agg_out[s * 32 + lane], xd);
    if (lane == 0) {
        atomicAdd(&g_cnt_in[d], 1);
        atomicAdd(&g_cnt_out[s], 1);
    }
}

// =================== pipelined SIMT GEMM (fp32, cp.async) ===================
// out = [x | agg_in/cnt | agg_out/cnt] @ Wpre + bias
// BM=128, BN=128, BK=32, 256 threads, 8x8/thread, double-buffered A(regs) + B(cp.async).
__global__ __launch_bounds__(256, 2)
void gemm_kernel(const float4* __restrict__ x4,
                 const float* __restrict__ bself,
                 const float* __restrict__ bs2d,
                 const float* __restrict__ bd2s,
                 float* __restrict__ out, int n) {
    __shared__ float As[2][32][132];   // k-major, padded: conflict-free
    __shared__ float Bs[2][32][128];
    __shared__ float rcpin[128], rcpout[128];

    const int tid  = threadIdx.x;
    const int row0 = blockIdx.x * 128;

    if (tid < 128) {
        int r = row0 + tid;
        float ci = 1.f, co = 1.f;
        if (r < n) {
            ci = (float)max(g_cnt_in[r], 1);
            co = (float)max(g_cnt_out[r], 1);
        }
        rcpin[tid]  = 1.f / ci;
        rcpout[tid] = 1.f / co;
    }

    const int tx = tid & 15, ty = tid >> 4;
    float acc[8][8];
#pragma unroll
    for (int i = 0; i < 8; i++)
#pragma unroll
        for (int j = 0; j < 8; j++) acc[i][j] = 0.f;

    // A-prefetch registers: idx = tid + i*256 -> row = idx>>3, q = idx&7
    float4 ra[4];
    auto loadA = [&](int kc) {
        const int seg  = kc >> 2;            // 0:x 1:agg_in 2:agg_out
        const int base = (kc & 3) * 8;
        const float4* src = seg == 0 ? x4
                          : (seg == 1 ? (const float4*)g_agg_in
                                      : (const float4*)g_agg_out);
#pragma unroll
        for (int i = 0; i < 4; i++) {
            int idx = tid + i * 256;
            int row = idx >> 3, q = idx & 7;
            int r = row0 + row;
            ra[i] = (r < n) ? src[r * 32 + base + q]
                            : make_float4(0.f, 0.f, 0.f, 0.f);
        }
    };

    // ---- prologue: B0 via cp.async, A0 via regs ----
    {
        uint32_t sb0 = smem_u32(&Bs[0][0][0]);
#pragma unroll
        for (int i = 0; i < 4; i++) {
            int idx = tid + i * 256;       // float4 index 0..1023
            cp_async16(sb0 + idx * 16, &g_Wpre[idx * 4]);
        }
        cp_commit();
    }
    loadA(0);

    for (int kc = 0; kc < 12; kc++) {
        const int buf = kc & 1;
        const int seg = kc >> 2;

        // 1) store prefetched A -> As[buf], transposed + scaled
#pragma unroll
        for (int i = 0; i < 4; i++) {
            int idx = tid + i * 256;
            int row = idx >> 3, q = idx & 7;
            float sc = 1.f;
            if (seg == 1) sc = rcpin[row];
            else if (seg == 2) sc = rcpout[row];
            float4 v = ra[i];
            As[buf][q * 4 + 0][row] = v.x * sc;
            As[buf][q * 4 + 1][row] = v.y * sc;
            As[buf][q * 4 + 2][row] = v.z * sc;
            As[buf][q * 4 + 3][row] = v.w * sc;
        }
        // 2) ensure B[buf] landed, 3) barrier
        cp_wait0();
        __syncthreads();

        // 4) issue next B + prefetch next A (fully overlapped with compute)
        if (kc < 11) {
            uint32_t sbn = smem_u32(&Bs[buf ^ 1][0][0]);
            const float* gb = &g_Wpre[(kc + 1) * 4096];
#pragma unroll
            for (int i = 0; i < 4; i++) {
                int idx = tid + i * 256;
                cp_async16(sbn + idx * 16, gb + idx * 4);
            }
            cp_commit();
            loadA(kc + 1);
        }

        // 5) compute 32 k-steps
#pragma unroll
        for (int k = 0; k < 32; k++) {
            float a[8], b[8];
            *(float4*)(a)     = *(const float4*)&As[buf][k][ty * 8];
            *(float4*)(a + 4) = *(const float4*)&As[buf][k][ty * 8 + 4];
            *(float4*)(b)     = *(const float4*)&Bs[buf][k][tx * 8];
            *(float4*)(b + 4) = *(const float4*)&Bs[buf][k][tx * 8 + 4];
#pragma unroll
            for (int ii = 0; ii < 8; ii++)
#pragma unroll
                for (int jj = 0; jj < 8; jj++)
                    acc[ii][jj] += a[ii] * b[jj];
        }
    }

    // ---- epilogue: bias + store ----
    float bias[8];
#pragma unroll
    for (int jj = 0; jj < 8; jj++) {
        int j = tx * 8 + jj;
        bias[jj] = bself[j] + 0.5f * (bs2d[j] + bd2s[j]);
    }
#pragma unroll
    for (int ii = 0; ii < 8; ii++) {
        int r = row0 + ty * 8 + ii;
        if (r < n) {
            float4 v0, v1;
            v0.x = acc[ii][0] + bias[0]; v0.y = acc[ii][1] + bias[1];
            v0.z = acc[ii][2] + bias[2]; v0.w = acc[ii][3] + bias[3];
            v1.x = acc[ii][4] + bias[4]; v1.y = acc[ii][5] + bias[5];
            v1.z = acc[ii][6] + bias[6]; v1.w = acc[ii][7] + bias[7];
            *(float4*)&out[r * 128 + tx * 8]     = v0;
            *(float4*)&out[r * 128 + tx * 8 + 4] = v1;
        }
    }
}

// ================================ launch ===================================
extern "C" void kernel_launch(void* const* d_in, const int* in_sizes, int n_in,
                              void* d_out, int out_size) {
    const float* x     = (const float*)d_in[0];
    const float* Wself = (const float*)d_in[1];
    const float* bself = (const float*)d_in[2];
    const float* Ws2d  = (const float*)d_in[3];
    const float* bs2d  = (const float*)d_in[4];
    const float* Wd2s  = (const float*)d_in[5];
    const float* bd2s  = (const float*)d_in[6];
    const void*  ei    = d_in[7];

    const int n = in_sizes[0] / 128;
    const int E = in_sizes[7] / 2;

    float* out = (float*)d_out;

    detect_kernel<<<1, 32>>>((const long long*)ei, E, n);
    zero_kernel<<<2048, 256>>>(n);
    prep_w_kernel<<<(12 * 4096 + 255) / 256, 256>>>(Wself, Ws2d, Wd2s);

    int eblocks = (E * 32 + 255) / 256;   // one warp per edge
    edge_kernel<<<eblocks, 256>>>((const float4*)x, ei, E);

    int gblocks = (n + 127) / 128;
    gemm_kernel<<<gblocks, 256>>>((const float4*)x, bself, bs2d, bd2s, out, n);
}